// round 13
// baseline (speedup 1.0000x reference)
#include <cuda_runtime.h>
#include <cuda_bf16.h>

// AdderVDSR collapses analytically (established R0-R2, rel_err 1.2e-7):
//   adder_conv = -(sum of 576 |.|) < 0 strictly, relu(neg) == 0 exactly,
//   so all 16 adder blocks emit zeros and
//   out[b,c] = out_b[c] + pixel_shuffle(conv3x3(x, up_w) + up_b, r=2).
//
// Grid optimum mapped: 384 CTAs 6.3-6.5us / 192 CTAs 5.82us / 96 CTAs 6.02us.
// R12 keeps the 192-CTA / 2-outputs-per-thread optimum but makes the two
// rows ADJACENT (i, i+1): input rows gi = i-1..i+2 overlap, so 4 row-slices
// feed both accumulations (was 6 disjoint), and each slice is 1 float2 + 2
// edge scalars (was 4 predicated scalars). 72 -> 36 LDG/thread, FMAs equal.

__global__ __launch_bounds__(256) void adder_vdsr_collapsed(
    const float* __restrict__ x,      // [2,3,128,128]
    const float* __restrict__ up_w,   // [12,3,3,3]
    const float* __restrict__ up_b,   // [12]
    const float* __restrict__ out_b,  // [3]
    float* __restrict__ out)          // [2,3,256,256]
{
    const int tx = threadIdx.x;                 // 0..63 -> conv col pair 2tx
    const int ty = threadIdx.y;                 // 0..3
    const int i  = blockIdx.y * 8 + ty * 2;     // conv rows i, i+1
    const int z  = blockIdx.z;                  // 0..11
    const int b  = z / 6;
    const int cp = z % 6;
    const int c  = cp >> 1;
    const int p  = cp & 1;
    const int o0 = 4 * c + 2 * p;
    const int j0 = 2 * tx;

    // 54 CTA-uniform weights (uniform __ldg, L1 broadcast), loaded once.
    float w0[27], w1[27];
    const float* W = up_w + o0 * 27;
    #pragma unroll
    for (int k = 0; k < 27; k++) {
        w0[k] = __ldg(W + k);
        w1[k] = __ldg(W + 27 + k);
    }
    const float bias0 = __ldg(up_b + o0);
    const float bias1 = __ldg(up_b + o0 + 1);
    const float ob    = __ldg(out_b + c);

    // Accumulators: rows {i, i+1} x channels {o0, o0+1} x cols {j0, j0+1}.
    float a00 = bias0, a01 = bias0, a10 = bias1, a11 = bias1;  // row i
    float b00 = bias0, b01 = bias0, b10 = bias1, b11 = bias1;  // row i+1

    #pragma unroll
    for (int cin = 0; cin < 3; cin++) {
        const float* xp = x + (size_t)(b * 3 + cin) * 128 * 128;

        // 4 input row-slices gi = i-1 .. i+2, cols j0-1 .. j0+2.
        float v[4][4];
        #pragma unroll
        for (int kr = 0; kr < 4; kr++) {
            const int gi = i - 1 + kr;
            const bool rok = (gi >= 0) & (gi < 128);
            const float* rowp = xp + gi * 128;
            if (rok) {
                v[kr][0] = (tx > 0) ? __ldg(rowp + j0 - 1) : 0.0f;
                float2 m = __ldg(reinterpret_cast<const float2*>(rowp + j0));
                v[kr][1] = m.x;
                v[kr][2] = m.y;
                v[kr][3] = (tx < 63) ? __ldg(rowp + j0 + 2) : 0.0f;
            } else {
                v[kr][0] = v[kr][1] = v[kr][2] = v[kr][3] = 0.0f;
            }
        }

        #pragma unroll
        for (int ki = 0; ki < 3; ki++) {
            #pragma unroll
            for (int kj = 0; kj < 3; kj++) {
                const float wv0 = w0[cin * 9 + ki * 3 + kj];
                const float wv1 = w1[cin * 9 + ki * 3 + kj];
                // row i uses slices ki; row i+1 uses slices ki+1.
                a00 = fmaf(v[ki][kj],         wv0, a00);
                a10 = fmaf(v[ki][kj],         wv1, a10);
                a01 = fmaf(v[ki][kj + 1],     wv0, a01);
                a11 = fmaf(v[ki][kj + 1],     wv1, a11);
                b00 = fmaf(v[ki + 1][kj],     wv0, b00);
                b10 = fmaf(v[ki + 1][kj],     wv1, b10);
                b01 = fmaf(v[ki + 1][kj + 1], wv0, b01);
                b11 = fmaf(v[ki + 1][kj + 1], wv1, b11);
            }
        }
    }

    // Pixel shuffle: conv (r, 2tx..2tx+1) x ch {o0,o0+1} ->
    // out row (2r+p), cols 4tx..4tx+3, channel c. Two STG.128.
    float* base = out + (size_t)(b * 3 + c) * 256 * 256;
    reinterpret_cast<float4*>(base + (size_t)(2 * i + p) * 256)[tx] =
        make_float4(a00 + ob, a10 + ob, a01 + ob, a11 + ob);
    reinterpret_cast<float4*>(base + (size_t)(2 * i + 2 + p) * 256)[tx] =
        make_float4(b00 + ob, b10 + ob, b01 + ob, b11 + ob);
}

extern "C" void kernel_launch(void* const* d_in, const int* in_sizes, int n_in,
                              void* d_out, int out_size) {
    (void)in_sizes; (void)n_in; (void)out_size;
    const float* x     = (const float*)d_in[0];
    const float* up_w  = (const float*)d_in[1];
    const float* up_b  = (const float*)d_in[2];
    const float* out_b = (const float*)d_in[7];
    float* out = (float*)d_out;

    dim3 grid(1, 16, 12);   // 192 CTAs (optimum): y = 8-row slab, z = b,c,p
    dim3 block(64, 4);      // 256 threads; each thread does rows 2ty, 2ty+1
    adder_vdsr_collapsed<<<grid, block>>>(x, up_w, up_b, out_b, out);
}

// round 14
// speedup vs baseline: 1.0938x; 1.0938x over previous
#include <cuda_runtime.h>
#include <cuda_bf16.h>

// FINAL (R13 = R10, the measured-best configuration).
//
// AdderVDSR collapses analytically (established R0-R2, rel_err 1.2e-7):
//   adder_conv = -(sum of 576 |.|) < 0 strictly on this data, and
//   relu(negative) == 0 exactly, so the first adder block outputs exact
//   zeros and all 16 stacked blocks keep h == 0. The whole network reduces to
//   out[b,c] = out_b[c] + pixel_shuffle(conv3x3(x, up_w) + up_b, r=2).
//
// Optimization history (ncu dur):
//   R2 smem-tile 12ch/thread           8.80us
//   R4 384 CTAs, 1 float4/thread       6.27us
//   R5/R6/R8 LDG restructurings        6.3-6.9us (body hidden under ramp)
//   R10 192 CTAs, 2 float4/thread      5.82us  <- grid optimum (min)
//   R11  96 CTAs, 4 float4/thread      6.02us
//   R12 192 CTAs, 36 LDG/thread        6.24us  (L1 10.5% yet slower ->
//        proof the floor is launch + dispatch ramp, not the body)
//
// Layout: CTA owns (batch b, color c, row parity p) -> conv channels
// {4c+2p, 4c+2p+1}; thread computes rows {i, i+4} x cols {2tx, 2tx+1} and
// writes two float4s with the pixel-shuffle interleave
// [o0@2j, o1@2j, o0@2j+1, o1@2j+1].

__global__ __launch_bounds__(256) void adder_vdsr_collapsed(
    const float* __restrict__ x,      // [2,3,128,128]
    const float* __restrict__ up_w,   // [12,3,3,3]
    const float* __restrict__ up_b,   // [12]
    const float* __restrict__ out_b,  // [3]
    float* __restrict__ out)          // [2,3,256,256]
{
    const int tx = threadIdx.x;                 // 0..63 -> conv col pair 2tx
    const int ty = threadIdx.y;                 // 0..3
    const int i0 = blockIdx.y * 8 + ty;         // rows i0 and i0+4
    const int z  = blockIdx.z;                  // 0..11
    const int b  = z / 6;
    const int cp = z % 6;
    const int c  = cp >> 1;
    const int p  = cp & 1;
    const int o0 = 4 * c + 2 * p;
    const int j0 = 2 * tx;

    // 54 CTA-uniform weights (uniform __ldg, L1 broadcast) - loaded once,
    // reused for both output rows.
    float w0[27], w1[27];
    const float* W = up_w + o0 * 27;
    #pragma unroll
    for (int k = 0; k < 27; k++) {
        w0[k] = __ldg(W + k);
        w1[k] = __ldg(W + 27 + k);
    }
    const float bias0 = __ldg(up_b + o0);
    const float bias1 = __ldg(up_b + o0 + 1);
    const float ob    = __ldg(out_b + c);

    #pragma unroll
    for (int rr = 0; rr < 2; rr++) {
        const int i = i0 + 4 * rr;

        float a00 = bias0, a01 = bias0;   // channel o0,   px {2tx, 2tx+1}
        float a10 = bias1, a11 = bias1;   // channel o0+1

        #pragma unroll
        for (int cin = 0; cin < 3; cin++) {
            const float* xp = x + (size_t)(b * 3 + cin) * 128 * 128;
            float v[3][4];
            #pragma unroll
            for (int ki = 0; ki < 3; ki++) {
                const int gi = i - 1 + ki;
                const bool rok = (gi >= 0) & (gi < 128);
                #pragma unroll
                for (int kc = 0; kc < 4; kc++) {
                    const int gj = j0 - 1 + kc;
                    v[ki][kc] = (rok && gj >= 0 && gj < 128)
                              ? __ldg(xp + gi * 128 + gj) : 0.0f;
                }
            }
            #pragma unroll
            for (int ki = 0; ki < 3; ki++) {
                #pragma unroll
                for (int kj = 0; kj < 3; kj++) {
                    const float wv0 = w0[cin * 9 + ki * 3 + kj];
                    const float wv1 = w1[cin * 9 + ki * 3 + kj];
                    a00 = fmaf(v[ki][kj],     wv0, a00);
                    a10 = fmaf(v[ki][kj],     wv1, a10);
                    a01 = fmaf(v[ki][kj + 1], wv0, a01);
                    a11 = fmaf(v[ki][kj + 1], wv1, a11);
                }
            }
        }

        // Pixel shuffle: conv (i, 2tx..2tx+1) x ch {o0,o0+1} ->
        // out row (2i+p), cols 4tx..4tx+3, channel c. One STG.128.
        float4 r = make_float4(a00 + ob, a10 + ob, a01 + ob, a11 + ob);
        float* row = out + ((size_t)(b * 3 + c) * 256 + (2 * i + p)) * 256;
        reinterpret_cast<float4*>(row)[tx] = r;
    }
}

extern "C" void kernel_launch(void* const* d_in, const int* in_sizes, int n_in,
                              void* d_out, int out_size) {
    (void)in_sizes; (void)n_in; (void)out_size;
    const float* x     = (const float*)d_in[0];
    const float* up_w  = (const float*)d_in[1];
    const float* up_b  = (const float*)d_in[2];
    const float* out_b = (const float*)d_in[7];
    float* out = (float*)d_out;

    dim3 grid(1, 16, 12);   // 192 CTAs (grid optimum): y = 8-row slab, z = b,c,p
    dim3 block(64, 4);      // 256 threads; each thread does rows ty and ty+4
    adder_vdsr_collapsed<<<grid, block>>>(x, up_w, up_b, out_b, out);
}

// round 15
// speedup vs baseline: 1.3592x; 1.2427x over previous
#include <cuda_runtime.h>
#include <cuda_bf16.h>

// FINAL — AdderVDSR, collapsed analytically.
//
// Math (established R0-R2, rel_err 1.2e-7):
//   adder_conv = -(sum of 576 |patch - w|) < 0 strictly on this data, and
//   relu(negative) == 0 exactly, so the first adder block emits exact zeros
//   and all 16 stacked blocks keep h == 0. The network reduces to
//   out[b,c] = out_b[c] + pixel_shuffle(conv3x3(x, up_w) + up_b, r=2)
//   — a ~1400x work reduction, and the only optimization that mattered.
//
// Hardware model (established R4-R14): the collapsed kernel is launch-bound.
//   ncu dur across 7 structural variants (LDG/thread 36..90, CTAs 96..768,
//   block 128/256, regs 32..128): 5.82-6.50us, identical-source repeats
//   differ by 0.32us -> one noise cluster around ~6.1us, every pipe <35%,
//   DRAM 0.8%. T_ovh ~5000 cyc of ~7000 total; the body is hidden (R12:
//   halving LDGs moved L1 20%->10.5% with zero time gain).
//
// This is the measured-best configuration (R10): 192 CTAs (grid optimum of
// the 96/192/384 sweep), 2 float4 outputs per thread, 54 register-resident
// CTA-uniform weights.

__global__ __launch_bounds__(256) void adder_vdsr_collapsed(
    const float* __restrict__ x,      // [2,3,128,128]
    const float* __restrict__ up_w,   // [12,3,3,3]
    const float* __restrict__ up_b,   // [12]
    const float* __restrict__ out_b,  // [3]
    float* __restrict__ out)          // [2,3,256,256]
{
    const int tx = threadIdx.x;                 // 0..63 -> conv col pair 2tx
    const int ty = threadIdx.y;                 // 0..3
    const int i0 = blockIdx.y * 8 + ty;         // rows i0 and i0+4
    const int z  = blockIdx.z;                  // 0..11
    const int b  = z / 6;
    const int cp = z % 6;
    const int c  = cp >> 1;
    const int p  = cp & 1;
    const int o0 = 4 * c + 2 * p;
    const int j0 = 2 * tx;

    // 54 CTA-uniform weights (uniform __ldg, L1 broadcast) - loaded once,
    // reused for both output rows.
    float w0[27], w1[27];
    const float* W = up_w + o0 * 27;
    #pragma unroll
    for (int k = 0; k < 27; k++) {
        w0[k] = __ldg(W + k);
        w1[k] = __ldg(W + 27 + k);
    }
    const float bias0 = __ldg(up_b + o0);
    const float bias1 = __ldg(up_b + o0 + 1);
    const float ob    = __ldg(out_b + c);

    #pragma unroll
    for (int rr = 0; rr < 2; rr++) {
        const int i = i0 + 4 * rr;

        float a00 = bias0, a01 = bias0;   // channel o0,   px {2tx, 2tx+1}
        float a10 = bias1, a11 = bias1;   // channel o0+1

        #pragma unroll
        for (int cin = 0; cin < 3; cin++) {
            const float* xp = x + (size_t)(b * 3 + cin) * 128 * 128;
            float v[3][4];
            #pragma unroll
            for (int ki = 0; ki < 3; ki++) {
                const int gi = i - 1 + ki;
                const bool rok = (gi >= 0) & (gi < 128);
                #pragma unroll
                for (int kc = 0; kc < 4; kc++) {
                    const int gj = j0 - 1 + kc;
                    v[ki][kc] = (rok && gj >= 0 && gj < 128)
                              ? __ldg(xp + gi * 128 + gj) : 0.0f;
                }
            }
            #pragma unroll
            for (int ki = 0; ki < 3; ki++) {
                #pragma unroll
                for (int kj = 0; kj < 3; kj++) {
                    const float wv0 = w0[cin * 9 + ki * 3 + kj];
                    const float wv1 = w1[cin * 9 + ki * 3 + kj];
                    a00 = fmaf(v[ki][kj],     wv0, a00);
                    a10 = fmaf(v[ki][kj],     wv1, a10);
                    a01 = fmaf(v[ki][kj + 1], wv0, a01);
                    a11 = fmaf(v[ki][kj + 1], wv1, a11);
                }
            }
        }

        // Pixel shuffle: conv (i, 2tx..2tx+1) x ch {o0,o0+1} ->
        // out row (2i+p), cols 4tx..4tx+3, channel c. One STG.128.
        float4 r = make_float4(a00 + ob, a10 + ob, a01 + ob, a11 + ob);
        float* row = out + ((size_t)(b * 3 + c) * 256 + (2 * i + p)) * 256;
        reinterpret_cast<float4*>(row)[tx] = r;
    }
}

extern "C" void kernel_launch(void* const* d_in, const int* in_sizes, int n_in,
                              void* d_out, int out_size) {
    (void)in_sizes; (void)n_in; (void)out_size;
    const float* x     = (const float*)d_in[0];
    const float* up_w  = (const float*)d_in[1];
    const float* up_b  = (const float*)d_in[2];
    const float* out_b = (const float*)d_in[7];
    float* out = (float*)d_out;

    dim3 grid(1, 16, 12);   // 192 CTAs (grid optimum): y = 8-row slab, z = b,c,p
    dim3 block(64, 4);      // 256 threads; each thread does rows ty and ty+4
    adder_vdsr_collapsed<<<grid, block>>>(x, up_w, up_b, out_b, out);
}